// round 17
// baseline (speedup 1.0000x reference)
#include <cuda_runtime.h>
#include <math_constants.h>

// Problem constants
#define BQ    2
#define NQ    8192
#define KNN   16
#define QPW   2                        // queries per warp
#define WPB   16                       // warps per block
#define BLOCK 512
#define QPB   (QPW * WPB)              // 32 queries per block
#define TILE  2048                     // candidates per smem tile (SoA, 32 KB)
#define BLOCKS_PER_BATCH (NQ / QPB)    // 256
#define NBLK  (BQ * BLOCKS_PER_BATCH)  // 512
#define FULL  0xffffffffu
#define TOTAL_EDGES ((double)(BQ) * (double)(NQ) * (double)(KNN))

__device__ float g_partials[NBLK];

// ---- packed f32x2 helpers (each half IEEE-RN, bit-identical to scalar) ----
typedef unsigned long long u64;
__device__ __forceinline__ u64 pack2(float lo, float hi) {
    u64 r;
    asm("mov.b64 %0, {%1, %2};" : "=l"(r)
        : "r"(__float_as_uint(lo)), "r"(__float_as_uint(hi)));
    return r;
}
__device__ __forceinline__ void unpack2(u64 v, float& lo, float& hi) {
    unsigned a, b;
    asm("mov.b64 {%0, %1}, %2;" : "=r"(a), "=r"(b) : "l"(v));
    lo = __uint_as_float(a); hi = __uint_as_float(b);
}
__device__ __forceinline__ u64 fma2(u64 a, u64 b, u64 c) {
    u64 r; asm("fma.rn.f32x2 %0, %1, %2, %3;" : "=l"(r) : "l"(a), "l"(b), "l"(c));
    return r;
}
__device__ __forceinline__ u64 mul2(u64 a, u64 b) {
    u64 r; asm("mul.rn.f32x2 %0, %1, %2;" : "=l"(r) : "l"(a), "l"(b));
    return r;
}
__device__ __forceinline__ u64 add2(u64 a, u64 b) {
    u64 r; asm("add.rn.f32x2 %0, %1, %2;" : "=l"(r) : "l"(a), "l"(b));
    return r;
}

// Lexicographic insert of (v, vi) into the warp-distributed sorted top-16
// (lane l<16 holds the (l+1)-th smallest (d2, idx)). Order-independent: the
// final 16-set is the unique lex-minimal set -> matches jax.lax.top_k
// (ascending d2, ties by lower index) for ANY candidate processing order.
// Stale/equal-but-higher-index values give pos==16 -> no-op. (Proven exact
// in R14/R15, rel_err 0.0.)
__device__ __forceinline__ void insert_lex(float v, int vi, int lane,
                                           float& kd, int& ki)
{
    const unsigned le = __ballot_sync(FULL,
        (lane < KNN) && ((kd < v) || (kd == v && ki < vi)));
    const int pos = __popc(le);
    const float kdu = __shfl_up_sync(FULL, kd, 1);
    const int   kiu = __shfl_up_sync(FULL, ki, 1);
    if (lane >= pos) {
        kd = (lane == pos) ? v  : kdu;
        ki = (lane == pos) ? vi : kiu;
    }
}

// Full ascending bitonic sort of one value per lane (network proven R10-R12).
__device__ __forceinline__ float bitonic_sort32(float val, int lane)
{
#pragma unroll
    for (int k = 2; k <= 32; k <<= 1) {
#pragma unroll
        for (int j = k >> 1; j >= 1; j >>= 1) {
            float o = __shfl_xor_sync(FULL, val, j);
            bool up = ((lane & k) == 0);
            bool tm = (up == ((lane & j) == 0));
            val = tm ? fminf(val, o) : fmaxf(val, o);
        }
    }
    return val;
}

__global__ __launch_bounds__(BLOCK, 2)
void knn_loss_kernel(const float* __restrict__ points_ref,
                     const float* __restrict__ points)
{
    // SoA tile: lane handles candidate pair (s+2*lane, s+2*lane+1) via LDS.64
    __shared__ float Xs[TILE], Ys[TILE], Zs[TILE], Ws[TILE];
    __shared__ float wsum[WPB];

    const int tid  = threadIdx.x;
    const int wid  = tid >> 5;
    const int lane = tid & 31;
    const int b    = blockIdx.x / BLOCKS_PER_BATCH;
    const int q0   = (blockIdx.x % BLOCKS_PER_BATCH) * QPB + wid * QPW;

    const float* __restrict__ pr = points_ref + (size_t)b * NQ * 3;
    const float* __restrict__ pp = points     + (size_t)b * NQ * 3;

    // Query constants, packed (broadcast loads)
    u64 Qx[QPW], Qy[QPW], Qz[QPW], S2[QPW];
#pragma unroll
    for (int q = 0; q < QPW; ++q) {
        const float x = pr[(q0 + q) * 3 + 0];
        const float y = pr[(q0 + q) * 3 + 1];
        const float z = pr[(q0 + q) * 3 + 2];
        const float s = x * x + y * y + z * z;   // same expansion as reference
        Qx[q] = pack2(x, x); Qy[q] = pack2(y, y);
        Qz[q] = pack2(z, z); S2[q] = pack2(s, s);
    }
    const u64 N2 = pack2(-2.0f, -2.0f);

    float kd[QPW], thr[QPW];
    int   ki[QPW], thri[QPW];
#pragma unroll
    for (int q = 0; q < QPW; ++q) {
        kd[q] = CUDART_INF_F; ki[q] = 0x7fffffff;
        thr[q] = CUDART_INF_F; thri[q] = (int)0x80000000;
    }

    for (int t0 = 0; t0 < NQ; t0 += TILE) {
        __syncthreads();
        for (int i = tid; i < TILE; i += BLOCK) {
            const int   m = t0 + i;
            const float x = pr[m * 3 + 0];
            const float y = pr[m * 3 + 1];
            const float z = pr[m * 3 + 2];
            Xs[i] = x; Ys[i] = y; Zs[i] = z;
            Ws[i] = x * x + y * y + z * z;
        }
        __syncthreads();

        if (t0 == 0) {
            // ---- Warm start: vote-free per-lane min over tile 0 ----
            float mn[QPW];
#pragma unroll
            for (int q = 0; q < QPW; ++q) mn[q] = CUDART_INF_F;
            for (int s = 0; s < TILE; s += 64) {
                const u64 xv = reinterpret_cast<const u64*>(Xs + s)[lane];
                const u64 yv = reinterpret_cast<const u64*>(Ys + s)[lane];
                const u64 zv = reinterpret_cast<const u64*>(Zs + s)[lane];
                const u64 wv = reinterpret_cast<const u64*>(Ws + s)[lane];
#pragma unroll
                for (int q = 0; q < QPW; ++q) {
                    u64 dA = fma2(N2, fma2(Qx[q], xv, fma2(Qy[q], yv, mul2(Qz[q], zv))),
                                  add2(S2[q], wv));
                    float d0, d1; unpack2(dA, d0, d1);
                    const unsigned rel = (unsigned)(q0 + q - s);
                    if (rel < 64u && lane == (int)(rel >> 1)) {
                        if ((rel & 1u) == 0) d0 = CUDART_INF_F; else d1 = CUDART_INF_F;
                    }
                    mn[q] = fminf(mn[q], fminf(d0, d1));
                }
            }
            // T = 16th-smallest of 32 lane minima: upper bound on true 16th-NN
            // d2 (16 lanes -> 16 distinct non-self candidates <= T).
#pragma unroll
            for (int q = 0; q < QPW; ++q) {
                float T = __shfl_sync(FULL, bitonic_sort32(mn[q], lane), KNN - 1);
                thr[q]  = __int_as_float(__float_as_int(T) + 1); // admit d2<=T
                thri[q] = (int)0x80000000;
            }
        }

        // ---- Filtered scan: 64 candidates (32 pairs) x 2 queries per step ----
        for (int s = 0; s < TILE; s += 64) {
            const int sg = t0 + s;
            const u64 xv = reinterpret_cast<const u64*>(Xs + s)[lane];
            const u64 yv = reinterpret_cast<const u64*>(Ys + s)[lane];
            const u64 zv = reinterpret_cast<const u64*>(Zs + s)[lane];
            const u64 wv = reinterpret_cast<const u64*>(Ws + s)[lane];

            float d0[QPW], d1[QPW];
#pragma unroll
            for (int q = 0; q < QPW; ++q) {
                u64 dA = fma2(N2, fma2(Qx[q], xv, fma2(Qy[q], yv, mul2(Qz[q], zv))),
                              add2(S2[q], wv));
                unpack2(dA, d0[q], d1[q]);
            }
            // Self-exclusion (rare warp-uniform branch; queries consecutive)
            if ((unsigned)(q0 + QPW - 1 - sg) < (unsigned)(64 + QPW - 1)) {
#pragma unroll
                for (int q = 0; q < QPW; ++q) {
                    const unsigned rel = (unsigned)(q0 + q - sg);
                    if (rel < 64u && lane == (int)(rel >> 1)) {
                        if ((rel & 1u) == 0) d0[q] = CUDART_INF_F;
                        else                 d1[q] = CUDART_INF_F;
                    }
                }
            }

            // Admission: d <= thr is a superset of lex-qualifying; equal-but-
            // higher-index admits become pos==16 no-ops inside insert_lex.
            bool any = false;
#pragma unroll
            for (int q = 0; q < QPW; ++q)
                any |= (d0[q] <= thr[q]) | (d1[q] <= thr[q]);
            if (__ballot_sync(FULL, any)) {
#pragma unroll
                for (int q = 0; q < QPW; ++q) {
                    unsigned m0 = __ballot_sync(FULL, d0[q] <= thr[q]);
                    while (m0) {
                        const int   src = __ffs(m0) - 1;
                        const float v   = __shfl_sync(FULL, d0[q], src);
                        insert_lex(v, sg + 2 * src, lane, kd[q], ki[q]);
                        m0 &= m0 - 1;
                    }
                    unsigned m1 = __ballot_sync(FULL, d1[q] <= thr[q]);
                    while (m1) {
                        const int   src = __ffs(m1) - 1;
                        const float v   = __shfl_sync(FULL, d1[q], src);
                        insert_lex(v, sg + 2 * src + 1, lane, kd[q], ki[q]);
                        m1 &= m1 - 1;
                    }
                    // Refresh lex threshold once per hit-step (only tightens).
                    thr[q]  = __shfl_sync(FULL, kd[q], KNN - 1);
                    thri[q] = __shfl_sync(FULL, ki[q], KNN - 1);
                }
            }
        }
    }

    // ---- Edge lengths + L1: lanes 0..15 hold one neighbor per query ----
    float partial = 0.0f;
    if (lane < KNN) {
#pragma unroll
        for (int q = 0; q < QPW; ++q) {
            const int qn = q0 + q;
            const int nb = ki[q];
            const float qx = pr[qn * 3 + 0], qy = pr[qn * 3 + 1], qz = pr[qn * 3 + 2];
            float rx = pr[nb * 3 + 0] - qx;
            float ry = pr[nb * 3 + 1] - qy;
            float rz = pr[nb * 3 + 2] - qz;
            float dref = sqrtf(rx * rx + ry * ry + rz * rz);
            const float px0 = pp[qn * 3 + 0], py0 = pp[qn * 3 + 1], pz0 = pp[qn * 3 + 2];
            float px = pp[nb * 3 + 0] - px0;
            float py = pp[nb * 3 + 1] - py0;
            float pz = pp[nb * 3 + 2] - pz0;
            float dprd = sqrtf(px * px + py * py + pz * pz);
            partial += fabsf(dref - dprd);
        }
    }

    // Deterministic warp + block reduction
#pragma unroll
    for (int o = 16; o > 0; o >>= 1)
        partial += __shfl_xor_sync(FULL, partial, o);
    if (lane == 0) wsum[wid] = partial;
    __syncthreads();

    if (wid == 0) {
        float s = (lane < WPB) ? wsum[lane] : 0.0f;
#pragma unroll
        for (int o = 16; o > 0; o >>= 1)
            s += __shfl_xor_sync(FULL, s, o);
        if (lane == 0) g_partials[blockIdx.x] = s;
    }
}

__global__ void finalize_kernel(float* __restrict__ out)
{
    __shared__ double sred[256];
    int t = threadIdx.x;
    double s = 0.0;
    for (int i = t; i < NBLK; i += 256) s += (double)g_partials[i];
    sred[t] = s;
    __syncthreads();
#pragma unroll
    for (int st = 128; st > 0; st >>= 1) {
        if (t < st) sred[t] += sred[t + st];
        __syncthreads();
    }
    if (t == 0) out[0] = (float)(sred[0] / TOTAL_EDGES);
}

extern "C" void kernel_launch(void* const* d_in, const int* in_sizes, int n_in,
                              void* d_out, int out_size)
{
    (void)in_sizes; (void)n_in; (void)out_size;
    const float* points_ref = (const float*)d_in[0];
    const float* points     = (const float*)d_in[1];
    knn_loss_kernel<<<NBLK, BLOCK>>>(points_ref, points);
    finalize_kernel<<<1, 256>>>((float*)d_out);
}